// round 13
// baseline (speedup 1.0000x reference)
#include <cuda_runtime.h>
#include <math.h>

// ---------------- problem constants ----------------
// SPARSE_SHAPE=(468,468,1), WINDOW=(12,12,1), BATCH=4
// full id = b*3200 + wx*80 + wy*2 + z ; dataset has z==0 always,
// so compressed counting id = id>>1 = b*1600 + wx*40 + wy in [0, 6400)
#define WC 6400
#define MAXN 310016
#define NT 148           // one rank block per SM
#define MAXT 150
#define TILEMAX 2112
#define NWALK 8          // walk warps; warps 8..15 stream pe

// ---------------- static scratch ----------------
__device__ int g_win0[MAXN];
__device__ int g_win1[MAXN];
__device__ int g_rank0[MAXN];
__device__ int g_rank1[MAXN];
__device__ unsigned g_cw[MAXN];  // packed coords: x0|y0<<8|x1<<16|y1<<24
__device__ unsigned short g_h0[(long)MAXT * WC];
__device__ unsigned short g_h1[(long)MAXT * WC];
__device__ int g_counts0[WC];
__device__ int g_counts1[WC];
__device__ __align__(16) float g_tab[12 * 64];

__device__ __forceinline__ void level_target(int n, int& lvl, int& tgt) {
    if (n < 16)      { lvl = 0; tgt = 16; }
    else if (n < 32) { lvl = 1; tgt = 32; }
    else if (n < 64) { lvl = 2; tgt = 64; }
    else             { lvl = 3; tgt = 144; }
}

// Shared: float tab[768]; u16 cnt[NWALK*WC]; u16 swin[TILEMAX];
//         u16 srank[TILEMAX]; u8 skeep[TILEMAX]
#define SMEM_RANK_BYTES (768 * 4 + NWALK * WC * 2 + TILEMAX * 2 + TILEMAX * 2 + TILEMAX)

__device__ __forceinline__ void build_tab(float* tab, int tid, bool write_global) {
    if (tid < 384) {
        int v = tid >> 5, fi = tid & 31;
        float inv = exp2f((float)fi * 0.41524101186092029f);  // 10000^(fi/32)
        float arg = (float)(v - 6) / inv;
        float s, c;
        sincosf(arg, &s, &c);
        tab[v * 64 + 2 * fi]     = s;
        tab[v * 64 + 2 * fi + 1] = c;
        if (write_global) {
            g_tab[v * 64 + 2 * fi]     = s;
            g_tab[v * 64 + 2 * fi + 1] = c;
        }
    }
}

// Warp-collective: one pe row (128 floats) for token tok. WHICH: 0=pe0, 1=pe1.
template <int WHICH, bool VEC4>
__device__ __forceinline__ void emit_pe(const float* tab, float* __restrict__ out,
                                        long Nl, int tok, unsigned cw, int lane) {
    int half = lane >> 4;
    int v = (WHICH == 0) ? (half ? ((cw >> 8) & 255) : (cw & 255))
                         : (half ? ((cw >> 24) & 255) : ((cw >> 16) & 255));
    long base = (WHICH == 0 ? 135L : 263L) * Nl;
    if (VEC4) {
        int col = lane & 15;
        float4 p = ((const float4*)tab)[v * 16 + col];
        __stcs(&((float4*)(out + base))[(long)tok * 32 + lane], p);
    } else {
#pragma unroll
        for (int k = 0; k < 4; k++) {
            int c = lane * 4 + k;
            out[base + (long)tok * 128 + c] = tab[v * 64 + (c & 63)];
        }
    }
}

// ---------------- pass 0: prepare + rank walk (8 warps) || pe0 first-half (8 warps) ----------------
template <bool VEC4>
__global__ void __launch_bounds__(512) k_rank0(const int* __restrict__ coords,
                                               float* __restrict__ out,
                                               int N, int TILE, int H0) {
    extern __shared__ float shf[];
    float* tab = shf;
    unsigned short* cnt = (unsigned short*)(shf + 768);
    unsigned short* swin = cnt + NWALK * WC;
    unsigned short* srank = swin + TILEMAX;
    int t = blockIdx.x, tid = threadIdx.x;
    int warp = tid >> 5, lane = tid & 31;
    int start = t * TILE;
    int len = min(TILE, N - start);
    if (len < 0) len = 0;
    long Nl = N;

    build_tab(tab, tid, t == 0);

    for (int j = tid; j < NWALK * WC / 2; j += 512) ((unsigned*)cnt)[j] = 0;

    for (int j = tid; j < len; j += 512) {
        int i = start + j;
        int4 c4 = ((const int4*)coords)[i];     // (b, z, y, x)
        int b = c4.x, z = c4.y, y = c4.z, x = c4.w;
        int cx0 = x + 12, cy0 = y + 12;         // do_shift=False (sz=0)
        int cx1 = x + 6,  cy1 = y + 6;          // do_shift=True  (sz=0)
        int w0 = b * 3200 + (cx0 / 12) * 80 + (cy0 / 12) * 2 + z;
        int w1 = b * 3200 + (cx1 / 12) * 80 + (cy1 / 12) * 2 + z;
        g_win0[i] = w0;
        g_win1[i] = w1;
        g_cw[i] = (unsigned)(cx0 % 12) | ((unsigned)(cy0 % 12) << 8) |
                  ((unsigned)(cx1 % 12) << 16) | ((unsigned)(cy1 % 12) << 24);
        swin[j] = (unsigned short)(w0 >> 1);    // compressed (z==0)
    }
    __syncthreads();

    int CH = (len + NWALK - 1) / NWALK;
    if (CH < 1) CH = 1;
    if (warp < NWALK) {
        unsigned short* mycnt = cnt + warp * WC;
        int clo = warp * CH, chi = min(clo + CH, len);
        for (int base = clo; base < chi; base += 32) {
            int j = base + lane;
            bool inb = j < chi;
            int w = inb ? (int)swin[j] : (WC + lane);
            unsigned peers = __match_any_sync(0xffffffffu, w);
            int leader = __ffs(peers) - 1;
            int r = __popc(peers & ((1u << lane) - 1u));
            int basec = 0;
            if (inb && lane == leader) {
                basec = (int)mycnt[w];
                mycnt[w] = (unsigned short)(basec + __popc(peers));
            }
            basec = __shfl_sync(0xffffffffu, basec, leader);
            if (inb) srank[j] = (unsigned short)(basec + r);
            __syncwarp();
        }
    } else {
        int wp = warp - NWALK;
        int jhi = min(len, H0);
        for (int j = wp; j < jhi; j += 16 - NWALK) {
            int tok = start + j;
            unsigned cw = g_cw[tok];
            emit_pe<0, VEC4>(tab, out, Nl, tok, cw, lane);
        }
    }
    __syncthreads();

    unsigned short* hrow = g_h0 + (long)t * WC;
    for (int w = tid; w < WC; w += 512) {
        int run = 0;
#pragma unroll
        for (int W = 0; W < NWALK; W++) {
            int v = (int)cnt[W * WC + w];
            cnt[W * WC + w] = (unsigned short)run;
            run += v;
        }
        hrow[w] = (unsigned short)run;
    }
    __syncthreads();

    for (int j = tid; j < len; j += 512) {
        int W = j / CH;
        g_rank0[start + j] = (int)srank[j] + (int)cnt[W * WC + (int)swin[j]];
    }
}

// ---------------- pass 1: finalize rank0/keep + walk among kept || pe1 first-half ----------------
template <bool VEC4>
__global__ void __launch_bounds__(512) k_rank1(float* __restrict__ out,
                                               int N, int TILE, int H0) {
    extern __shared__ float shf[];
    float* tab = shf;
    unsigned short* cnt = (unsigned short*)(shf + 768);
    unsigned short* swin = cnt + NWALK * WC;
    unsigned short* srank = swin + TILEMAX;
    unsigned char* skeep = (unsigned char*)(srank + TILEMAX);
    int t = blockIdx.x, tid = threadIdx.x;
    int warp = tid >> 5, lane = tid & 31;
    int start = t * TILE;
    int len = min(TILE, N - start);
    if (len < 0) len = 0;
    long Nl = N;
    const unsigned short* pref0 = g_h0 + (long)t * WC;

    build_tab(tab, tid, false);

    for (int j = tid; j < NWALK * WC / 2; j += 512) ((unsigned*)cnt)[j] = 0;

    for (int j = tid; j < len; j += 512) {
        int i = start + j;
        int c0 = g_win0[i] >> 1;
        int r0 = g_rank0[i] + (int)__ldg(&pref0[c0]);   // finalize pass-0 rank
        g_rank0[i] = r0;
        int lvl, tgt;
        level_target(g_counts0[c0], lvl, tgt);
        skeep[j] = (r0 < tgt) ? 1 : 0;
        swin[j] = (unsigned short)(g_win1[i] >> 1);
    }
    __syncthreads();

    int CH = (len + NWALK - 1) / NWALK;
    if (CH < 1) CH = 1;
    if (warp < NWALK) {
        unsigned short* mycnt = cnt + warp * WC;
        int clo = warp * CH, chi = min(clo + CH, len);
        for (int base = clo; base < chi; base += 32) {
            int j = base + lane;
            bool inb = j < chi;
            bool valid = inb && skeep[j];
            int w = valid ? (int)swin[j] : (WC + lane);
            unsigned peers = __match_any_sync(0xffffffffu, w);
            int leader = __ffs(peers) - 1;
            int r = __popc(peers & ((1u << lane) - 1u));
            int basec = 0;
            if (valid && lane == leader) {
                basec = (int)mycnt[w];
                mycnt[w] = (unsigned short)(basec + __popc(peers));
            }
            basec = __shfl_sync(0xffffffffu, basec, leader);
            if (inb) srank[j] = (unsigned short)(valid ? (basec + r) : 0);
            __syncwarp();
        }
    } else {
        int wp = warp - NWALK;
        int jhi = min(len, H0);
        for (int j = wp; j < jhi; j += 16 - NWALK) {
            int tok = start + j;
            unsigned cw = g_cw[tok];
            emit_pe<1, VEC4>(tab, out, Nl, tok, cw, lane);
        }
    }
    __syncthreads();

    unsigned short* hrow = g_h1 + (long)t * WC;
    for (int w = tid; w < WC; w += 512) {
        int run = 0;
#pragma unroll
        for (int W = 0; W < NWALK; W++) {
            int v = (int)cnt[W * WC + w];
            cnt[W * WC + w] = (unsigned short)run;
            run += v;
        }
        hrow[w] = (unsigned short)run;
    }
    __syncthreads();

    for (int j = tid; j < len; j += 512) {
        int W = j / CH;
        g_rank1[start + j] = (int)srank[j] + (int)cnt[W * WC + (int)swin[j]];
    }
}

// ---------------- scan over tiles (16 windows/block) + pe second-half streaming ----------------
template <int PASS, bool VEC4>
__global__ void __launch_bounds__(256) k_scan(float* __restrict__ out,
                                              int N, int T, int TILE, int H0) {
    __shared__ unsigned short s[MAXT * 17];
    unsigned short* hist = (PASS == 0) ? g_h0 : g_h1;
    int* counts = (PASS == 0) ? g_counts0 : g_counts1;
    int w0 = blockIdx.x * 16;
    int tid = threadIdx.x;

    int nq = T * 4;
    for (int i = tid; i < nq; i += 256) {
        int t = i >> 2, q = (i & 3) * 4;
        ushort4 v = *(const ushort4*)&hist[(long)t * WC + w0 + q];
        s[t * 17 + q + 0] = v.x;
        s[t * 17 + q + 1] = v.y;
        s[t * 17 + q + 2] = v.z;
        s[t * 17 + q + 3] = v.w;
    }
    __syncthreads();

    int w = tid >> 4, sub = tid & 15;
    int chunk = (T + 15) >> 4;
    int lo = sub * chunk, hi = min(lo + chunk, T);
    int partial = 0;
    for (int t = lo; t < hi; t++) partial += (int)s[t * 17 + w];
    int inc = partial;
#pragma unroll
    for (int d = 1; d < 16; d <<= 1) {
        int v = __shfl_up_sync(0xffffffffu, inc, d, 16);
        if (sub >= d) inc += v;
    }
    int run = inc - partial;
    for (int t = lo; t < hi; t++) {
        int v = (int)s[t * 17 + w];
        s[t * 17 + w] = (unsigned short)run;
        run += v;
    }
    if (sub == 15) counts[w0 + w] = inc;
    __syncthreads();

    for (int i = tid; i < nq; i += 256) {
        int t = i >> 2, q = (i & 3) * 4;
        ushort4 v;
        v.x = s[t * 17 + q + 0];
        v.y = s[t * 17 + q + 1];
        v.z = s[t * 17 + q + 2];
        v.w = s[t * 17 + q + 3];
        *(ushort4*)&hist[(long)t * WC + w0 + q] = v;
    }

    // ---- pe streaming tail: second halves of all tiles (PASS 0: pe0, PASS 1: pe1)
    int S0 = TILE - H0;
    if (S0 > 0) {
        int Nv = T * S0;
        int per = (Nv + (int)gridDim.x - 1) / (int)gridDim.x;
        int vlo = blockIdx.x * per;
        int vhi = min(vlo + per, Nv);
        int warp = tid >> 5, lane = tid & 31;
        long Nl = N;
        for (int v = vlo + warp; v < vhi; v += 8) {
            int t = v / S0, o = v - t * S0;
            int tok = t * TILE + H0 + o;
            if (tok < N) {
                unsigned cw = g_cw[tok];
                emit_pe<PASS, VEC4>(g_tab, out, Nl, tok, cw, lane);
            }
        }
    }
}

// ---------------- feat masked copy + 7 scalar rows ----------------
template <bool VEC4>
__global__ void __launch_bounds__(256) k_feat(const float* __restrict__ feat,
                                              float* __restrict__ out, int N, int TILE) {
    int warp = threadIdx.x >> 5;
    int lane = threadIdx.x & 31;
    int tok = blockIdx.x * (blockDim.x >> 5) + warp;
    if (tok >= N) return;
    long Nl = N;

    int w0 = g_win0[tok], w1 = g_win1[tok];
    int c0 = w0 >> 1, c1 = w1 >> 1;
    int r0 = g_rank0[tok];
    int lvl0, t0;
    level_target(g_counts0[c0], lvl0, t0);
    bool keep1 = r0 < t0;
    int dl1 = -1, r1o = -1;
    bool keepF = false;
    if (keep1) {
        int t = tok / TILE;
        int r1 = g_rank1[tok] + (int)g_h1[(long)t * WC + c1];
        int lvl, tg;
        level_target(g_counts1[c1], lvl, tg);
        dl1 = lvl;
        r1o = r1;
        keepF = r1 < tg;
    }
    if (lane < 7) {
        float sv;
        switch (lane) {
            case 0: sv = keepF ? 1.0f : 0.0f; break;
            case 1: sv = (float)w0; break;
            case 2: sv = (float)w1; break;
            case 3: sv = (float)lvl0; break;
            case 4: sv = (float)dl1; break;
            case 5: sv = (float)r0; break;
            default: sv = (float)r1o; break;
        }
        __stcs(&out[(long)(128 + lane) * Nl + tok], sv);
    }

    bool kf = keepF;
    if (VEC4) {
        float4 f = __ldcs(&((const float4*)feat)[(long)tok * 32 + lane]);
        if (!kf) { f.x = 0.f; f.y = 0.f; f.z = 0.f; f.w = 0.f; }
        __stcs(&((float4*)out)[(long)tok * 32 + lane], f);
    } else {
#pragma unroll
        for (int k = 0; k < 4; k++) {
            int c = lane * 4 + k;
            float f = feat[(long)tok * 128 + c];
            out[(long)tok * 128 + c] = kf ? f : 0.f;
        }
    }
}

// ---------------- launch ----------------
extern "C" void kernel_launch(void* const* d_in, const int* in_sizes, int n_in,
                              void* d_out, int out_size) {
    const float* feat = (const float*)d_in[0];
    const int* coords = (const int*)d_in[1];
    float* out = (float*)d_out;
    int N = in_sizes[1] / 4;
    if (N > MAXN) N = MAXN;
    int TILE = (N + NT - 1) / NT;
    if (TILE < 32) TILE = 32;
    if (TILE > TILEMAX) TILE = TILEMAX;
    int T = (N + TILE - 1) / TILE;
    int H0 = (TILE + 1) / 2;

    cudaFuncSetAttribute(k_rank0<true>,  cudaFuncAttributeMaxDynamicSharedMemorySize, SMEM_RANK_BYTES);
    cudaFuncSetAttribute(k_rank0<false>, cudaFuncAttributeMaxDynamicSharedMemorySize, SMEM_RANK_BYTES);
    cudaFuncSetAttribute(k_rank1<true>,  cudaFuncAttributeMaxDynamicSharedMemorySize, SMEM_RANK_BYTES);
    cudaFuncSetAttribute(k_rank1<false>, cudaFuncAttributeMaxDynamicSharedMemorySize, SMEM_RANK_BYTES);

    int vb = (N + 7) / 8;
    bool vec4 = (N & 3) == 0;

    if (vec4) {
        k_rank0<true><<<T, 512, SMEM_RANK_BYTES>>>(coords, out, N, TILE, H0);
        k_scan<0, true><<<WC / 16, 256>>>(out, N, T, TILE, H0);
        k_rank1<true><<<T, 512, SMEM_RANK_BYTES>>>(out, N, TILE, H0);
        k_scan<1, true><<<WC / 16, 256>>>(out, N, T, TILE, H0);
        k_feat<true><<<vb, 256>>>(feat, out, N, TILE);
    } else {
        k_rank0<false><<<T, 512, SMEM_RANK_BYTES>>>(coords, out, N, TILE, H0);
        k_scan<0, false><<<WC / 16, 256>>>(out, N, T, TILE, H0);
        k_rank1<false><<<T, 512, SMEM_RANK_BYTES>>>(out, N, TILE, H0);
        k_scan<1, false><<<WC / 16, 256>>>(out, N, T, TILE, H0);
        k_feat<false><<<vb, 256>>>(feat, out, N, TILE);
    }
}

// round 14
// speedup vs baseline: 1.1116x; 1.1116x over previous
#include <cuda_runtime.h>
#include <math.h>

// ---------------- problem constants ----------------
// SPARSE_SHAPE=(468,468,1), WINDOW=(12,12,1), BATCH=4
// full id = b*3200 + wx*80 + wy*2 + z ; dataset has z==0 always,
// so compressed counting id = id>>1 = b*1600 + wx*40 + wy in [0, 6400)
#define WC 6400
#define MAXN 310016
#define NT 148           // one rank block (1/SM), 16-warp hierarchical rank
#define MAXT 150
#define TILEMAX 2112
#define NWARP 16

// ---------------- static scratch ----------------
__device__ int g_win0[MAXN];
__device__ int g_win1[MAXN];
__device__ int g_rank0[MAXN];
__device__ int g_rank1[MAXN];
__device__ unsigned g_cw[MAXN];  // packed coords: x0|y0<<8|x1<<16|y1<<24
__device__ unsigned short g_h0[(long)MAXT * WC];
__device__ unsigned short g_h1[(long)MAXT * WC];
__device__ int g_counts0[WC];
__device__ int g_counts1[WC];
__device__ __align__(16) float g_tab[12 * 64];

__device__ __forceinline__ void level_target(int n, int& lvl, int& tgt) {
    if (n < 16)      { lvl = 0; tgt = 16; }
    else if (n < 32) { lvl = 1; tgt = 32; }
    else if (n < 64) { lvl = 2; tgt = 64; }
    else             { lvl = 3; tgt = 144; }
}

// Shared: u16 cnt[NWARP*WC]; u16 swin[TILEMAX]; u16 srank[TILEMAX]; u8 skeep[TILEMAX]
#define SMEM_RANK_BYTES (NWARP * WC * 2 + TILEMAX * 2 + TILEMAX * 2 + TILEMAX)

template <int PASS>
__device__ __forceinline__ void rank_core(
    unsigned short* cnt, unsigned short* swin, unsigned short* srank,
    const unsigned char* skeep, int* grank, unsigned short* hrow,
    int start, int len, int tid)
{
    int warp = tid >> 5, lane = tid & 31;
    int CH = (len + NWARP - 1) >> 4;
    if (CH < 1) CH = 1;

    for (int j = tid; j < NWARP * WC / 2; j += 512) ((unsigned*)cnt)[j] = 0;
    __syncthreads();

    {
        unsigned short* mycnt = cnt + warp * WC;
        int clo = warp * CH;
        int chi = min(clo + CH, len);
        for (int base = clo; base < chi; base += 32) {
            int j = base + lane;
            bool inb = j < chi;
            bool valid = inb && (PASS == 0 || skeep[j]);
            int w = valid ? (int)swin[j] : (WC + lane);
            unsigned peers = __match_any_sync(0xffffffffu, w);
            int leader = __ffs(peers) - 1;
            int r = __popc(peers & ((1u << lane) - 1u));
            int basec = 0;
            if (valid && lane == leader) {
                basec = (int)mycnt[w];
                mycnt[w] = (unsigned short)(basec + __popc(peers));
            }
            basec = __shfl_sync(0xffffffffu, basec, leader);
            if (inb) srank[j] = (unsigned short)(valid ? (basec + r) : 0);
            __syncwarp();
        }
    }
    __syncthreads();

    for (int w = tid; w < WC; w += 512) {
        int run = 0;
#pragma unroll
        for (int W = 0; W < NWARP; W++) {
            int v = (int)cnt[W * WC + w];
            cnt[W * WC + w] = (unsigned short)run;
            run += v;
        }
        hrow[w] = (unsigned short)run;
    }
    __syncthreads();

    for (int j = tid; j < len; j += 512) {
        int W = j / CH;
        grank[start + j] = (int)srank[j] + (int)cnt[W * WC + (int)swin[j]];
    }
}

// ---------------- pass 0: prepare + hierarchical rank + tile histogram ----------------
__global__ void __launch_bounds__(512) k_rank0(const int* __restrict__ coords, int N, int TILE) {
    extern __shared__ unsigned short sh16[];
    unsigned short* cnt = sh16;
    unsigned short* swin = sh16 + NWARP * WC;
    unsigned short* srank = swin + TILEMAX;
    int t = blockIdx.x, tid = threadIdx.x;
    int start = t * TILE;
    int len = min(TILE, N - start);
    if (len < 0) len = 0;

    if (t == 0 && tid < 384) {
        int v = tid >> 5, fi = tid & 31;
        float inv = exp2f((float)fi * 0.41524101186092029f);  // 10000^(fi/32)
        float arg = (float)(v - 6) / inv;
        float s, c;
        sincosf(arg, &s, &c);
        g_tab[v * 64 + 2 * fi]     = s;
        g_tab[v * 64 + 2 * fi + 1] = c;
    }

    for (int j = tid; j < len; j += 512) {
        int i = start + j;
        int4 c4 = ((const int4*)coords)[i];     // (b, z, y, x)
        int b = c4.x, z = c4.y, y = c4.z, x = c4.w;
        int cx0 = x + 12, cy0 = y + 12;         // do_shift=False (sz=0)
        int cx1 = x + 6,  cy1 = y + 6;          // do_shift=True  (sz=0)
        int w0 = b * 3200 + (cx0 / 12) * 80 + (cy0 / 12) * 2 + z;
        int w1 = b * 3200 + (cx1 / 12) * 80 + (cy1 / 12) * 2 + z;
        g_win0[i] = w0;
        g_win1[i] = w1;
        g_cw[i] = (unsigned)(cx0 % 12) | ((unsigned)(cy0 % 12) << 8) |
                  ((unsigned)(cx1 % 12) << 16) | ((unsigned)(cy1 % 12) << 24);
        swin[j] = (unsigned short)(w0 >> 1);    // compressed (z==0)
    }
    __syncthreads();

    rank_core<0>(cnt, swin, srank, (const unsigned char*)0,
                 g_rank0, g_h0 + (long)t * WC, start, len, tid);
}

// ---------------- pass 1: finalize rank0/keep + rank among kept in win1 ----------------
__global__ void __launch_bounds__(512) k_rank1(int N, int TILE) {
    extern __shared__ unsigned short sh16[];
    unsigned short* cnt = sh16;
    unsigned short* swin = sh16 + NWARP * WC;
    unsigned short* srank = swin + TILEMAX;
    unsigned char* skeep = (unsigned char*)(srank + TILEMAX);
    int t = blockIdx.x, tid = threadIdx.x;
    int start = t * TILE;
    int len = min(TILE, N - start);
    if (len < 0) len = 0;
    const unsigned short* pref0 = g_h0 + (long)t * WC;

    for (int j = tid; j < len; j += 512) {
        int i = start + j;
        int c0 = g_win0[i] >> 1;
        int r0 = g_rank0[i] + (int)__ldg(&pref0[c0]);
        g_rank0[i] = r0;
        int lvl, tgt;
        level_target(g_counts0[c0], lvl, tgt);
        skeep[j] = (r0 < tgt) ? 1 : 0;
        swin[j] = (unsigned short)(g_win1[i] >> 1);
    }
    __syncthreads();

    rank_core<1>(cnt, swin, srank, skeep,
                 g_rank1, g_h1 + (long)t * WC, start, len, tid);
}

// ---------------- parallel per-window exclusive scan over tiles ----------------
template <int PASS>
__global__ void __launch_bounds__(256) k_scan(int T) {
    __shared__ unsigned short s[MAXT * 17];
    unsigned short* hist = (PASS == 0) ? g_h0 : g_h1;
    int* counts = (PASS == 0) ? g_counts0 : g_counts1;
    int w0 = blockIdx.x * 16;
    int tid = threadIdx.x;

    int nq = T * 4;
    for (int i = tid; i < nq; i += 256) {
        int t = i >> 2, q = (i & 3) * 4;
        ushort4 v = *(const ushort4*)&hist[(long)t * WC + w0 + q];
        s[t * 17 + q + 0] = v.x;
        s[t * 17 + q + 1] = v.y;
        s[t * 17 + q + 2] = v.z;
        s[t * 17 + q + 3] = v.w;
    }
    __syncthreads();

    int w = tid >> 4, sub = tid & 15;
    int chunk = (T + 15) >> 4;
    int lo = sub * chunk, hi = min(lo + chunk, T);
    int partial = 0;
    for (int t = lo; t < hi; t++) partial += (int)s[t * 17 + w];
    int inc = partial;
#pragma unroll
    for (int d = 1; d < 16; d <<= 1) {
        int v = __shfl_up_sync(0xffffffffu, inc, d, 16);
        if (sub >= d) inc += v;
    }
    int run = inc - partial;
    for (int t = lo; t < hi; t++) {
        int v = (int)s[t * 17 + w];
        s[t * 17 + w] = (unsigned short)run;
        run += v;
    }
    if (sub == 15) counts[w0 + w] = inc;
    __syncthreads();

    for (int i = tid; i < nq; i += 256) {
        int t = i >> 2, q = (i & 3) * 4;
        ushort4 v;
        v.x = s[t * 17 + q + 0];
        v.y = s[t * 17 + q + 1];
        v.z = s[t * 17 + q + 2];
        v.w = s[t * 17 + q + 3];
        *(ushort4*)&hist[(long)t * WC + w0 + q] = v;
    }
}

// ---------------- pe0+pe1 streaming, persistent bounded grid ----------------
// Depends only on g_cw + g_tab (both ready after k_rank0). 296 blocks, 0 smem:
// co-resides with the rank/scan kernels instead of queueing in front of them.
template <bool VEC4>
__global__ void __launch_bounds__(256) k_pe(float* __restrict__ out, int N) {
    int warp = threadIdx.x >> 5;
    int lane = threadIdx.x & 31;
    int nwarps = (blockDim.x >> 5) * gridDim.x;
    int wid = blockIdx.x * (blockDim.x >> 5) + warp;
    long Nl = N;
    const float4* tab4 = (const float4*)g_tab;
    int half = lane >> 4, col = lane & 15;

    for (int tok = wid; tok < N; tok += nwarps) {
        unsigned cw = __ldg(&g_cw[tok]);
        int v0 = half ? ((cw >> 8) & 255) : (cw & 255);
        int v1 = half ? ((cw >> 24) & 255) : ((cw >> 16) & 255);
        if (VEC4) {
            float4 p0 = tab4[v0 * 16 + col];
            float4 p1 = tab4[v1 * 16 + col];
            __stcs(&((float4*)(out + 135 * Nl))[(long)tok * 32 + lane], p0);
            __stcs(&((float4*)(out + 263 * Nl))[(long)tok * 32 + lane], p1);
        } else {
#pragma unroll
            for (int k = 0; k < 4; k++) {
                int c = lane * 4 + k;
                int cc = c & 63;
                out[135 * Nl + (long)tok * 128 + c] = g_tab[v0 * 64 + cc];
                out[263 * Nl + (long)tok * 128 + c] = g_tab[v1 * 64 + cc];
            }
        }
    }
}

// ---------------- feat masked copy + 7 scalar rows ----------------
template <bool VEC4>
__global__ void __launch_bounds__(256) k_feat(const float* __restrict__ feat,
                                              float* __restrict__ out, int N, int TILE) {
    int warp = threadIdx.x >> 5;
    int lane = threadIdx.x & 31;
    int tok = blockIdx.x * (blockDim.x >> 5) + warp;
    if (tok >= N) return;
    long Nl = N;

    int w0 = g_win0[tok], w1 = g_win1[tok];
    int c0 = w0 >> 1, c1 = w1 >> 1;
    int r0 = g_rank0[tok];
    int lvl0, t0;
    level_target(g_counts0[c0], lvl0, t0);
    bool keep1 = r0 < t0;
    int dl1 = -1, r1o = -1;
    bool keepF = false;
    if (keep1) {
        int t = tok / TILE;
        int r1 = g_rank1[tok] + (int)g_h1[(long)t * WC + c1];
        int lvl, tg;
        level_target(g_counts1[c1], lvl, tg);
        dl1 = lvl;
        r1o = r1;
        keepF = r1 < tg;
    }
    if (lane < 7) {
        float sv;
        switch (lane) {
            case 0: sv = keepF ? 1.0f : 0.0f; break;
            case 1: sv = (float)w0; break;
            case 2: sv = (float)w1; break;
            case 3: sv = (float)lvl0; break;
            case 4: sv = (float)dl1; break;
            case 5: sv = (float)r0; break;
            default: sv = (float)r1o; break;
        }
        __stcs(&out[(long)(128 + lane) * Nl + tok], sv);
    }

    bool kf = keepF;
    if (VEC4) {
        float4 f = __ldcs(&((const float4*)feat)[(long)tok * 32 + lane]);
        if (!kf) { f.x = 0.f; f.y = 0.f; f.z = 0.f; f.w = 0.f; }
        __stcs(&((float4*)out)[(long)tok * 32 + lane], f);
    } else {
#pragma unroll
        for (int k = 0; k < 4; k++) {
            int c = lane * 4 + k;
            float f = feat[(long)tok * 128 + c];
            out[(long)tok * 128 + c] = kf ? f : 0.f;
        }
    }
}

// ---------------- launch ----------------
extern "C" void kernel_launch(void* const* d_in, const int* in_sizes, int n_in,
                              void* d_out, int out_size) {
    const float* feat = (const float*)d_in[0];
    const int* coords = (const int*)d_in[1];
    float* out = (float*)d_out;
    int N = in_sizes[1] / 4;
    if (N > MAXN) N = MAXN;
    int TILE = (N + NT - 1) / NT;
    if (TILE < 32) TILE = 32;
    if (TILE > TILEMAX) TILE = TILEMAX;
    int T = (N + TILE - 1) / TILE;

    static cudaStream_t sB = 0;
    static cudaEvent_t evF = 0, evJ = 0;
    if (!sB) {
        cudaStreamCreateWithFlags(&sB, cudaStreamNonBlocking);
        cudaEventCreateWithFlags(&evF, cudaEventDisableTiming);
        cudaEventCreateWithFlags(&evJ, cudaEventDisableTiming);
    }

    cudaFuncSetAttribute(k_rank0, cudaFuncAttributeMaxDynamicSharedMemorySize, SMEM_RANK_BYTES);
    cudaFuncSetAttribute(k_rank1, cudaFuncAttributeMaxDynamicSharedMemorySize, SMEM_RANK_BYTES);

    int vb = (N + 7) / 8;
    bool vec4 = (N & 3) == 0;

    k_rank0<<<T, 512, SMEM_RANK_BYTES>>>(coords, N, TILE);

    // fork: pe0+pe1 on side stream with a bounded persistent grid (296 blocks,
    // no smem) so it CO-RESIDES with the remaining bookkeeping kernels rather
    // than queueing 37k blocks in front of them (the round-11 failure).
    cudaEventRecord(evF, 0);
    cudaStreamWaitEvent(sB, evF, 0);
    if (vec4) k_pe<true><<<296, 256, 0, sB>>>(out, N);
    else      k_pe<false><<<296, 256, 0, sB>>>(out, N);
    cudaEventRecord(evJ, sB);

    // main chain runs concurrently with the pe streamer
    k_scan<0><<<WC / 16, 256>>>(T);
    k_rank1<<<T, 512, SMEM_RANK_BYTES>>>(N, TILE);
    k_scan<1><<<WC / 16, 256>>>(T);
    if (vec4) k_feat<true><<<vb, 256>>>(feat, out, N, TILE);
    else      k_feat<false><<<vb, 256>>>(feat, out, N, TILE);

    // join
    cudaStreamWaitEvent(0, evJ, 0);
}

// round 15
// speedup vs baseline: 1.2785x; 1.1501x over previous
#include <cuda_runtime.h>
#include <math.h>

// ---------------- problem constants ----------------
// SPARSE_SHAPE=(468,468,1), WINDOW=(12,12,1), BATCH=4
// full id = b*3200 + wx*80 + wy*2 + z ; dataset has z==0 always,
// so compressed counting id = id>>1 = b*1600 + wx*40 + wy in [0, 6400)
#define WC 6400
#define MAXN 310016
#define NT 148           // tiles == blocks; 1 block/SM (215KB smem), wave-1 resident
#define MAXT 150
#define TILEMAX 2112
#define NWARP 16

// ---------------- static scratch ----------------
__device__ int g_win0[MAXN];
__device__ int g_win1[MAXN];
__device__ int g_rank0[MAXN];
__device__ int g_rank1[MAXN];
__device__ unsigned g_cw[MAXN];  // packed coords: x0|y0<<8|x1<<16|y1<<24
__device__ unsigned short g_h0[(long)MAXT * WC];
__device__ unsigned short g_h1[(long)MAXT * WC];
__device__ int g_counts0[WC];
__device__ int g_counts1[WC];
__device__ __align__(16) float g_tab[12 * 64];

// grid barrier state (monotone generation; deterministic output)
__device__ unsigned g_barcnt = 0;
__device__ volatile unsigned g_bargen = 0;

__device__ __forceinline__ void level_target(int n, int& lvl, int& tgt) {
    if (n < 16)      { lvl = 0; tgt = 16; }
    else if (n < 32) { lvl = 1; tgt = 32; }
    else if (n < 64) { lvl = 2; tgt = 64; }
    else             { lvl = 3; tgt = 144; }
}

// CG-style software grid sync. Valid because the whole grid is resident
// (grid = NT blocks, 1 per SM). __threadfence (gpu scope) emits CCTL.IVALL
// on sm_103a -> post-barrier reads see other SMs' writes.
__device__ __forceinline__ void gsync() {
    __threadfence();
    __syncthreads();
    if (threadIdx.x == 0) {
        unsigned gen = g_bargen;
        if (atomicAdd(&g_barcnt, 1u) == gridDim.x - 1u) {
            g_barcnt = 0u;
            __threadfence();
            g_bargen = gen + 1u;
        } else {
            while (g_bargen == gen) {}
        }
        __threadfence();
    }
    __syncthreads();
}

// Shared: u16 cnt[NWARP*WC]; u16 swin[TILEMAX]; u16 srank[TILEMAX]; u8 skeep[TILEMAX]
#define SMEM_RANK_BYTES (NWARP * WC * 2 + TILEMAX * 2 + TILEMAX * 2 + TILEMAX)

template <int PASS>
__device__ __forceinline__ void rank_core(
    unsigned short* cnt, unsigned short* swin, unsigned short* srank,
    const unsigned char* skeep, int* grank, unsigned short* hrow,
    int start, int len, int tid)
{
    int warp = tid >> 5, lane = tid & 31;
    int CH = (len + NWARP - 1) >> 4;
    if (CH < 1) CH = 1;

    for (int j = tid; j < NWARP * WC / 2; j += 512) ((unsigned*)cnt)[j] = 0;
    __syncthreads();

    {
        unsigned short* mycnt = cnt + warp * WC;
        int clo = warp * CH;
        int chi = min(clo + CH, len);
        for (int base = clo; base < chi; base += 32) {
            int j = base + lane;
            bool inb = j < chi;
            bool valid = inb && (PASS == 0 || skeep[j]);
            int w = valid ? (int)swin[j] : (WC + lane);
            unsigned peers = __match_any_sync(0xffffffffu, w);
            int leader = __ffs(peers) - 1;
            int r = __popc(peers & ((1u << lane) - 1u));
            int basec = 0;
            if (valid && lane == leader) {
                basec = (int)mycnt[w];
                mycnt[w] = (unsigned short)(basec + __popc(peers));
            }
            basec = __shfl_sync(0xffffffffu, basec, leader);
            if (inb) srank[j] = (unsigned short)(valid ? (basec + r) : 0);
            __syncwarp();
        }
    }
    __syncthreads();

    for (int w = tid; w < WC; w += 512) {
        int run = 0;
#pragma unroll
        for (int W = 0; W < NWARP; W++) {
            int v = (int)cnt[W * WC + w];
            cnt[W * WC + w] = (unsigned short)run;
            run += v;
        }
        hrow[w] = (unsigned short)run;
    }
    __syncthreads();

    for (int j = tid; j < len; j += 512) {
        int W = j / CH;
        grank[start + j] = (int)srank[j] + (int)cnt[W * WC + (int)swin[j]];
    }
}

// In-kernel scan over tiles for this block's window slice (stage in smem).
__device__ __forceinline__ void scan_phase(unsigned short* stage,
                                           unsigned short* hist, int* counts, int T) {
    int nb = gridDim.x;
    int wpb = (WC + nb - 1) / nb;
    int wbase = blockIdx.x * wpb;
    int wnum = WC - wbase;
    if (wnum > wpb) wnum = wpb;
    if (wnum < 0) wnum = 0;
    int tot = T * wnum;

    for (int i = threadIdx.x; i < tot; i += 512) {
        int t = i / wnum, w = i - t * wnum;
        stage[t * wpb + w] = hist[(long)t * WC + wbase + w];
    }
    __syncthreads();

    int wloc = threadIdx.x >> 3, sub = threadIdx.x & 7;   // 8 lanes/window
    int chunk = (T + 7) >> 3;
    for (int wg = 0; wg < wnum; wg += 64) {
        int w = wg + wloc;
        if (w < wnum) {
            int lo = sub * chunk, hi = min(lo + chunk, T);
            int partial = 0;
            for (int t = lo; t < hi; t++) partial += (int)stage[t * wpb + w];
            int inc = partial;
#pragma unroll
            for (int d = 1; d < 8; d <<= 1) {
                int v = __shfl_up_sync(0xffffffffu, inc, d, 8);
                if (sub >= d) inc += v;
            }
            int run = inc - partial;
            for (int t = lo; t < hi; t++) {
                int v = (int)stage[t * wpb + w];
                stage[t * wpb + w] = (unsigned short)run;
                run += v;
            }
            if (sub == 7) counts[wbase + w] = inc;
        }
    }
    __syncthreads();

    for (int i = threadIdx.x; i < tot; i += 512) {
        int t = i / wnum, w = i - t * wnum;
        hist[(long)t * WC + wbase + w] = stage[t * wpb + w];
    }
}

// ---------------- fused bookkeeping: rank0 -> scan0 -> rank1 -> scan1 ----------------
__global__ void __launch_bounds__(512) k_book(const int* __restrict__ coords, int N, int TILE) {
    extern __shared__ unsigned short sh16[];
    unsigned short* cnt = sh16;                       // also scan staging
    unsigned short* swin = sh16 + NWARP * WC;
    unsigned short* srank = swin + TILEMAX;
    unsigned char* skeep = (unsigned char*)(srank + TILEMAX);
    int t = blockIdx.x, tid = threadIdx.x;
    int T = gridDim.x;
    int start = t * TILE;
    int len = min(TILE, N - start);
    if (len < 0) len = 0;

    // ---- phase A: prepare + rank0
    if (t == 0 && tid < 384) {
        int v = tid >> 5, fi = tid & 31;
        float inv = exp2f((float)fi * 0.41524101186092029f);  // 10000^(fi/32)
        float arg = (float)(v - 6) / inv;
        float s, c;
        sincosf(arg, &s, &c);
        g_tab[v * 64 + 2 * fi]     = s;
        g_tab[v * 64 + 2 * fi + 1] = c;
    }

    for (int j = tid; j < len; j += 512) {
        int i = start + j;
        int4 c4 = ((const int4*)coords)[i];     // (b, z, y, x)
        int b = c4.x, z = c4.y, y = c4.z, x = c4.w;
        int cx0 = x + 12, cy0 = y + 12;         // do_shift=False (sz=0)
        int cx1 = x + 6,  cy1 = y + 6;          // do_shift=True  (sz=0)
        int w0 = b * 3200 + (cx0 / 12) * 80 + (cy0 / 12) * 2 + z;
        int w1 = b * 3200 + (cx1 / 12) * 80 + (cy1 / 12) * 2 + z;
        g_win0[i] = w0;
        g_win1[i] = w1;
        g_cw[i] = (unsigned)(cx0 % 12) | ((unsigned)(cy0 % 12) << 8) |
                  ((unsigned)(cx1 % 12) << 16) | ((unsigned)(cy1 % 12) << 24);
        swin[j] = (unsigned short)(w0 >> 1);    // compressed (z==0)
    }
    __syncthreads();

    rank_core<0>(cnt, swin, srank, (const unsigned char*)0,
                 g_rank0, g_h0 + (long)t * WC, start, len, tid);

    gsync();
    // ---- phase B: scan0 (cnt region reused as staging)
    scan_phase(cnt, g_h0, g_counts0, T);
    gsync();

    // ---- phase C: finalize rank0/keep + rank1
    const unsigned short* pref0 = g_h0 + (long)t * WC;
    for (int j = tid; j < len; j += 512) {
        int i = start + j;
        int c0 = g_win0[i] >> 1;
        int r0 = g_rank0[i] + (int)pref0[c0];
        g_rank0[i] = r0;
        int lvl, tgt;
        level_target(g_counts0[c0], lvl, tgt);
        skeep[j] = (r0 < tgt) ? 1 : 0;
        swin[j] = (unsigned short)(g_win1[i] >> 1);
    }
    __syncthreads();

    rank_core<1>(cnt, swin, srank, skeep,
                 g_rank1, g_h1 + (long)t * WC, start, len, tid);

    gsync();
    // ---- phase D: scan1
    scan_phase(cnt, g_h1, g_counts1, T);
}

// ---------------- streaming outputs + fused scalars (EXACT round-10 kernel) ----------------
template <bool VEC4>
__global__ void __launch_bounds__(256) k_vec(const float* __restrict__ feat,
                                             float* __restrict__ out, int N, int TILE) {
    int warp = threadIdx.x >> 5;
    int lane = threadIdx.x & 31;
    int tok = blockIdx.x * (blockDim.x >> 5) + warp;
    if (tok >= N) return;
    long Nl = N;

    int w0 = g_win0[tok], w1 = g_win1[tok];
    int c0 = w0 >> 1, c1 = w1 >> 1;
    int r0 = g_rank0[tok];
    int lvl0, t0;
    level_target(g_counts0[c0], lvl0, t0);
    bool keep1 = r0 < t0;
    int dl1 = -1, r1o = -1;
    bool keepF = false;
    if (keep1) {
        int t = tok / TILE;
        int r1 = g_rank1[tok] + (int)g_h1[(long)t * WC + c1];
        int lvl, tg;
        level_target(g_counts1[c1], lvl, tg);
        dl1 = lvl;
        r1o = r1;
        keepF = r1 < tg;
    }
    if (lane < 7) {
        float sv;
        switch (lane) {
            case 0: sv = keepF ? 1.0f : 0.0f; break;
            case 1: sv = (float)w0; break;
            case 2: sv = (float)w1; break;
            case 3: sv = (float)lvl0; break;
            case 4: sv = (float)dl1; break;
            case 5: sv = (float)r0; break;
            default: sv = (float)r1o; break;
        }
        __stcs(&out[(long)(128 + lane) * Nl + tok], sv);
    }

    unsigned cw = g_cw[tok];
    int half = lane >> 4;
    int v0 = half ? ((cw >> 8) & 255) : (cw & 255);
    int v1 = half ? ((cw >> 24) & 255) : ((cw >> 16) & 255);
    bool kf = keepF;

    if (VEC4) {
        int col = lane & 15;
        float4 f = __ldcs(&((const float4*)feat)[(long)tok * 32 + lane]);
        if (!kf) { f.x = 0.f; f.y = 0.f; f.z = 0.f; f.w = 0.f; }
        __stcs(&((float4*)out)[(long)tok * 32 + lane], f);
        const float4* tab4 = (const float4*)g_tab;
        float4 p0 = tab4[v0 * 16 + col];
        float4 p1 = tab4[v1 * 16 + col];
        __stcs(&((float4*)(out + 135 * Nl))[(long)tok * 32 + lane], p0);
        __stcs(&((float4*)(out + 263 * Nl))[(long)tok * 32 + lane], p1);
    } else {
#pragma unroll
        for (int k = 0; k < 4; k++) {
            int c = lane * 4 + k;
            float f = feat[(long)tok * 128 + c];
            out[(long)tok * 128 + c] = kf ? f : 0.f;
            int cc = c & 63;
            out[135 * Nl + (long)tok * 128 + c] = g_tab[v0 * 64 + cc];
            out[263 * Nl + (long)tok * 128 + c] = g_tab[v1 * 64 + cc];
        }
    }
}

// ---------------- launch ----------------
extern "C" void kernel_launch(void* const* d_in, const int* in_sizes, int n_in,
                              void* d_out, int out_size) {
    const float* feat = (const float*)d_in[0];
    const int* coords = (const int*)d_in[1];
    float* out = (float*)d_out;
    int N = in_sizes[1] / 4;
    if (N > MAXN) N = MAXN;
    int TILE = (N + NT - 1) / NT;
    if (TILE < 32) TILE = 32;
    if (TILE > TILEMAX) TILE = TILEMAX;
    int T = (N + TILE - 1) / TILE;

    cudaFuncSetAttribute(k_book, cudaFuncAttributeMaxDynamicSharedMemorySize, SMEM_RANK_BYTES);

    k_book<<<T, 512, SMEM_RANK_BYTES>>>(coords, N, TILE);

    int vb = (N + 7) / 8;
    if ((N & 3) == 0) k_vec<true><<<vb, 256>>>(feat, out, N, TILE);
    else              k_vec<false><<<vb, 256>>>(feat, out, N, TILE);
}